// round 3
// baseline (speedup 1.0000x reference)
#include <cuda_runtime.h>
#include <cstdint>

// Problem constants (fixed shapes from reference)
#define Bq 4
#define Tt 4096
#define Dd 1024
#define Hh 16
#define Kh 64
#define Mtot (Bq*Tt)          // 16384

// Scratch (device globals: no allocation allowed)
__device__ float g_r[(size_t)Mtot * Dd];
__device__ float g_k[(size_t)Mtot * Dd];
__device__ float g_v[(size_t)Mtot * Dd];
__device__ float g_o[(size_t)Mtot * Dd];
__device__ float2 g_stats[Bq * Hh];

// ---------------------------------------------------------------------------
// GEMM 1: fused token-shift mix + projection.
//   A[m][d] = x[m][d]*tm[d] + x[m-1][d]*(1-tm[d])  (x[m-1]=0 at t==0)
//   C[m][e] = sum_d A[m][d] * W[e][d]   (torch Linear: x @ W^T)
// sel: 0 -> g_r (with sigmoid), 1 -> g_k, 2 -> g_v
// ---------------------------------------------------------------------------
#define BM 128
#define BN 128
#define BKT 16

__global__ __launch_bounds__(256)
void mix_proj_gemm(const float* __restrict__ x,
                   const float* __restrict__ tmix,
                   const float* __restrict__ W,
                   int sel)
{
    __shared__ float As[BKT][BM + 4];
    __shared__ float Bs[BKT][BN + 4];

    const int tid = threadIdx.x;
    const int m0 = blockIdx.x * BM;
    const int n0 = blockIdx.y * BN;
    const int tx = tid & 15;       // column group
    const int ty = tid >> 4;       // row group

    float acc[8][8];
    #pragma unroll
    for (int i = 0; i < 8; ++i)
        #pragma unroll
        for (int j = 0; j < 8; ++j) acc[i][j] = 0.f;

    for (int k0 = 0; k0 < Dd; k0 += BKT) {
        // ---- load A tile (fused mix), 512 float4 slots, 2 per thread ----
        #pragma unroll
        for (int it = 0; it < 2; ++it) {
            int s  = tid + it * 256;
            int m  = s >> 2;
            int d4 = (s & 3) << 2;
            int gm = m0 + m;
            int gd = k0 + d4;
            int t  = gm & (Tt - 1);
            float4 xv = *(const float4*)(x + (size_t)gm * Dd + gd);
            float4 xp = make_float4(0.f, 0.f, 0.f, 0.f);
            if (t != 0) xp = *(const float4*)(x + (size_t)(gm - 1) * Dd + gd);
            float4 tm = *(const float4*)(tmix + gd);
            As[d4 + 0][m] = xv.x * tm.x + xp.x * (1.f - tm.x);
            As[d4 + 1][m] = xv.y * tm.y + xp.y * (1.f - tm.y);
            As[d4 + 2][m] = xv.z * tm.z + xp.z * (1.f - tm.z);
            As[d4 + 3][m] = xv.w * tm.w + xp.w * (1.f - tm.w);
        }
        // ---- load B tile: Bs[d][e] = W[e][d] ----
        #pragma unroll
        for (int it = 0; it < 2; ++it) {
            int s  = tid + it * 256;
            int e  = s >> 2;
            int d4 = (s & 3) << 2;
            int ge = n0 + e;
            int gd = k0 + d4;
            float4 wv = *(const float4*)(W + (size_t)ge * Dd + gd);
            Bs[d4 + 0][e] = wv.x;
            Bs[d4 + 1][e] = wv.y;
            Bs[d4 + 2][e] = wv.z;
            Bs[d4 + 3][e] = wv.w;
        }
        __syncthreads();

        #pragma unroll
        for (int kk = 0; kk < BKT; ++kk) {
            float a[8], b[8];
            #pragma unroll
            for (int i = 0; i < 8; ++i) a[i] = As[kk][ty * 8 + i];
            #pragma unroll
            for (int j = 0; j < 8; ++j) b[j] = Bs[kk][tx * 8 + j];
            #pragma unroll
            for (int i = 0; i < 8; ++i)
                #pragma unroll
                for (int j = 0; j < 8; ++j)
                    acc[i][j] = fmaf(a[i], b[j], acc[i][j]);
        }
        __syncthreads();
    }

    float* out = (sel == 0) ? g_r : (sel == 1) ? g_k : g_v;
    const bool sig = (sel == 0);
    #pragma unroll
    for (int i = 0; i < 8; ++i) {
        int gm = m0 + ty * 8 + i;
        int ge = n0 + tx * 8;
        float c[8];
        #pragma unroll
        for (int j = 0; j < 8; ++j) {
            c[j] = acc[i][j];
            if (sig) c[j] = 1.f / (1.f + __expf(-c[j]));
        }
        *(float4*)(out + (size_t)gm * Dd + ge)     = make_float4(c[0], c[1], c[2], c[3]);
        *(float4*)(out + (size_t)gm * Dd + ge + 4) = make_float4(c[4], c[5], c[6], c[7]);
    }
}

// ---------------------------------------------------------------------------
// WKV scan: one thread per (b,h,kk) channel, sequential over T.
// Also accumulates GroupNorm sum / sumsq per (b,h) and writes stats.
// ---------------------------------------------------------------------------
__global__ __launch_bounds__(64)
void wkv_scan(const float* __restrict__ time_decay,
              const float* __restrict__ time_first)
{
    const int bh = blockIdx.x;          // 0..63
    const int b  = bh >> 4;
    const int h  = bh & 15;
    const int kk = threadIdx.x;         // 0..63

    const float w  = expf(-expf(time_decay[h * Kh + kk]));
    const float eu = expf(time_first[h * Kh + kk]);

    const size_t base = (size_t)b * Tt * Dd + h * Kh + kk;

    float num = 0.f, den = 0.f;
    float s1 = 0.f, s2 = 0.f;

    #pragma unroll 1
    for (int t0 = 0; t0 < Tt; t0 += 8) {
        float kt[8], vt[8], rt[8];
        #pragma unroll
        for (int j = 0; j < 8; ++j) {
            size_t idx = base + (size_t)(t0 + j) * Dd;
            kt[j] = g_k[idx];
            vt[j] = g_v[idx];
            rt[j] = g_r[idx];
        }
        #pragma unroll
        for (int j = 0; j < 8; ++j) {
            float ek  = __expf(kt[j]);
            float ekv = ek * vt[j];
            float eek = eu * ek;
            float wkv = __fdividef(num + eu * ekv, den + eek + 1e-9f);
            float o   = rt[j] * wkv;
            g_o[base + (size_t)(t0 + j) * Dd] = o;
            s1 += o;
            s2 += o * o;
            num = num * w + ekv;
            den = den * w + ek;
        }
    }

    // GroupNorm stats over (T,K) for this (b,h)
    __shared__ float sh1[64], sh2[64];
    sh1[kk] = s1;
    sh2[kk] = s2;
    __syncthreads();
    #pragma unroll
    for (int off = 32; off > 0; off >>= 1) {
        if (kk < off) {
            sh1[kk] += sh1[kk + off];
            sh2[kk] += sh2[kk + off];
        }
        __syncthreads();
    }
    if (kk == 0) {
        const float invN = 1.f / (float)(Tt * Kh);
        float mean = sh1[0] * invN;
        float var  = sh2[0] * invN - mean * mean;
        g_stats[bh] = make_float2(mean, rsqrtf(var + 1e-5f));
    }
}

// ---------------------------------------------------------------------------
// GEMM 2: fused GroupNorm-normalize + output projection.
//   A[m][d] = (g_o[m][d] - mu[b,h]) * rstd[b,h] * gw[d] + gb[d]
//   out[m][e] = sum_d A[m][d] * W_o[e][d]
// ---------------------------------------------------------------------------
__global__ __launch_bounds__(256)
void out_gemm(const float* __restrict__ Wo,
              const float* __restrict__ gw,
              const float* __restrict__ gb,
              float* __restrict__ out)
{
    __shared__ float As[BKT][BM + 4];
    __shared__ float Bs[BKT][BN + 4];

    const int tid = threadIdx.x;
    const int m0 = blockIdx.x * BM;
    const int n0 = blockIdx.y * BN;
    const int tx = tid & 15;
    const int ty = tid >> 4;

    float acc[8][8];
    #pragma unroll
    for (int i = 0; i < 8; ++i)
        #pragma unroll
        for (int j = 0; j < 8; ++j) acc[i][j] = 0.f;

    for (int k0 = 0; k0 < Dd; k0 += BKT) {
        #pragma unroll
        for (int it = 0; it < 2; ++it) {
            int s  = tid + it * 256;
            int m  = s >> 2;
            int d4 = (s & 3) << 2;
            int gm = m0 + m;
            int gd = k0 + d4;
            int b  = gm >> 12;              // T = 4096
            int h  = gd >> 6;               // K = 64 (same h across a float4)
            float2 st = g_stats[(b << 4) + h];
            float4 ov  = *(const float4*)(g_o + (size_t)gm * Dd + gd);
            float4 gwv = *(const float4*)(gw + gd);
            float4 gbv = *(const float4*)(gb + gd);
            As[d4 + 0][m] = (ov.x - st.x) * st.y * gwv.x + gbv.x;
            As[d4 + 1][m] = (ov.y - st.x) * st.y * gwv.y + gbv.y;
            As[d4 + 2][m] = (ov.z - st.x) * st.y * gwv.z + gbv.z;
            As[d4 + 3][m] = (ov.w - st.x) * st.y * gwv.w + gbv.w;
        }
        #pragma unroll
        for (int it = 0; it < 2; ++it) {
            int s  = tid + it * 256;
            int e  = s >> 2;
            int d4 = (s & 3) << 2;
            int ge = n0 + e;
            int gd = k0 + d4;
            float4 wv = *(const float4*)(Wo + (size_t)ge * Dd + gd);
            Bs[d4 + 0][e] = wv.x;
            Bs[d4 + 1][e] = wv.y;
            Bs[d4 + 2][e] = wv.z;
            Bs[d4 + 3][e] = wv.w;
        }
        __syncthreads();

        #pragma unroll
        for (int kk = 0; kk < BKT; ++kk) {
            float a[8], bb[8];
            #pragma unroll
            for (int i = 0; i < 8; ++i) a[i] = As[kk][ty * 8 + i];
            #pragma unroll
            for (int j = 0; j < 8; ++j) bb[j] = Bs[kk][tx * 8 + j];
            #pragma unroll
            for (int i = 0; i < 8; ++i)
                #pragma unroll
                for (int j = 0; j < 8; ++j)
                    acc[i][j] = fmaf(a[i], bb[j], acc[i][j]);
        }
        __syncthreads();
    }

    #pragma unroll
    for (int i = 0; i < 8; ++i) {
        int gm = m0 + ty * 8 + i;
        int ge = n0 + tx * 8;
        *(float4*)(out + (size_t)gm * Dd + ge) =
            make_float4(acc[i][0], acc[i][1], acc[i][2], acc[i][3]);
        *(float4*)(out + (size_t)gm * Dd + ge + 4) =
            make_float4(acc[i][4], acc[i][5], acc[i][6], acc[i][7]);
    }
}

// ---------------------------------------------------------------------------
// kernel_launch
// Input order (metadata): x, time_mix_r, time_mix_k, time_mix_v, time_decay,
//                         time_first, W_r, W_k, W_v, W_o, gn_weight, gn_bias
// ---------------------------------------------------------------------------
extern "C" void kernel_launch(void* const* d_in, const int* in_sizes, int n_in,
                              void* d_out, int out_size)
{
    const float* x   = (const float*)d_in[0];
    const float* tmr = (const float*)d_in[1];
    const float* tmk = (const float*)d_in[2];
    const float* tmv = (const float*)d_in[3];
    const float* td  = (const float*)d_in[4];
    const float* tf  = (const float*)d_in[5];
    const float* Wr  = (const float*)d_in[6];
    const float* Wk  = (const float*)d_in[7];
    const float* Wv  = (const float*)d_in[8];
    const float* Wo  = (const float*)d_in[9];
    const float* gw  = (const float*)d_in[10];
    const float* gb  = (const float*)d_in[11];
    float* out = (float*)d_out;

    dim3 grid(Mtot / BM, Dd / BN);   // (128, 8)
    dim3 block(256);

    mix_proj_gemm<<<grid, block>>>(x, tmr, Wr, 0);  // r (sigmoid)
    mix_proj_gemm<<<grid, block>>>(x, tmk, Wk, 1);  // k
    mix_proj_gemm<<<grid, block>>>(x, tmv, Wv, 2);  // v

    wkv_scan<<<Bq * Hh, Kh>>>(td, tf);

    out_gemm<<<grid, block>>>(Wo, gw, gb, out);
}

// round 4
// speedup vs baseline: 1.0068x; 1.0068x over previous
#include <cuda_runtime.h>
#include <cstdint>

// Problem constants (fixed shapes from reference)
#define Bq 4
#define Tt 4096
#define Dd 1024
#define Hh 16
#define Kh 64
#define Mtot (Bq*Tt)          // 16384

// Scratch (device globals: no allocation allowed)
__device__ float g_r[(size_t)Mtot * Dd];
__device__ float g_k[(size_t)Mtot * Dd];
__device__ float g_v[(size_t)Mtot * Dd];
__device__ float g_o[(size_t)Mtot * Dd];
__device__ float2 g_stats[Bq * Hh];

// ---------------------------------------------------------------------------
// GEMM 1: fused token-shift mix + projection.
//   A[m][d] = x[m][d]*tm[d] + x[m-1][d]*(1-tm[d])  (x[m-1]=0 at t==0)
//   C[m][e] = sum_d A[m][d] * W[e][d]   (torch Linear: x @ W^T)
// sel: 0 -> g_r (with sigmoid), 1 -> g_k, 2 -> g_v
// ---------------------------------------------------------------------------
#define BM 128
#define BN 128
#define BKT 16

__global__ __launch_bounds__(256)
void mix_proj_gemm(const float* __restrict__ x,
                   const float* __restrict__ tmix,
                   const float* __restrict__ W,
                   int sel)
{
    __shared__ float As[BKT][BM + 4];
    __shared__ float Bs[BKT][BN + 4];

    const int tid = threadIdx.x;
    const int m0 = blockIdx.x * BM;
    const int n0 = blockIdx.y * BN;
    const int tx = tid & 15;       // column group
    const int ty = tid >> 4;       // row group

    float acc[8][8];
    #pragma unroll
    for (int i = 0; i < 8; ++i)
        #pragma unroll
        for (int j = 0; j < 8; ++j) acc[i][j] = 0.f;

    for (int k0 = 0; k0 < Dd; k0 += BKT) {
        // ---- load A tile (fused mix), 512 float4 slots, 2 per thread ----
        #pragma unroll
        for (int it = 0; it < 2; ++it) {
            int s  = tid + it * 256;
            int m  = s >> 2;
            int d4 = (s & 3) << 2;
            int gm = m0 + m;
            int gd = k0 + d4;
            int t  = gm & (Tt - 1);
            float4 xv = *(const float4*)(x + (size_t)gm * Dd + gd);
            float4 xp = make_float4(0.f, 0.f, 0.f, 0.f);
            if (t != 0) xp = *(const float4*)(x + (size_t)(gm - 1) * Dd + gd);
            float4 tm = *(const float4*)(tmix + gd);
            As[d4 + 0][m] = xv.x * tm.x + xp.x * (1.f - tm.x);
            As[d4 + 1][m] = xv.y * tm.y + xp.y * (1.f - tm.y);
            As[d4 + 2][m] = xv.z * tm.z + xp.z * (1.f - tm.z);
            As[d4 + 3][m] = xv.w * tm.w + xp.w * (1.f - tm.w);
        }
        // ---- load B tile: Bs[d][e] = W[e][d] ----
        #pragma unroll
        for (int it = 0; it < 2; ++it) {
            int s  = tid + it * 256;
            int e  = s >> 2;
            int d4 = (s & 3) << 2;
            int ge = n0 + e;
            int gd = k0 + d4;
            float4 wv = *(const float4*)(W + (size_t)ge * Dd + gd);
            Bs[d4 + 0][e] = wv.x;
            Bs[d4 + 1][e] = wv.y;
            Bs[d4 + 2][e] = wv.z;
            Bs[d4 + 3][e] = wv.w;
        }
        __syncthreads();

        #pragma unroll
        for (int kk = 0; kk < BKT; ++kk) {
            float a[8], b[8];
            #pragma unroll
            for (int i = 0; i < 8; ++i) a[i] = As[kk][ty * 8 + i];
            #pragma unroll
            for (int j = 0; j < 8; ++j) b[j] = Bs[kk][tx * 8 + j];
            #pragma unroll
            for (int i = 0; i < 8; ++i)
                #pragma unroll
                for (int j = 0; j < 8; ++j)
                    acc[i][j] = fmaf(a[i], b[j], acc[i][j]);
        }
        __syncthreads();
    }

    float* out = (sel == 0) ? g_r : (sel == 1) ? g_k : g_v;
    const bool sig = (sel == 0);
    #pragma unroll
    for (int i = 0; i < 8; ++i) {
        int gm = m0 + ty * 8 + i;
        int ge = n0 + tx * 8;
        float c[8];
        #pragma unroll
        for (int j = 0; j < 8; ++j) {
            c[j] = acc[i][j];
            if (sig) c[j] = 1.f / (1.f + __expf(-c[j]));
        }
        *(float4*)(out + (size_t)gm * Dd + ge)     = make_float4(c[0], c[1], c[2], c[3]);
        *(float4*)(out + (size_t)gm * Dd + ge + 4) = make_float4(c[4], c[5], c[6], c[7]);
    }
}

// ---------------------------------------------------------------------------
// WKV scan: one thread per (b,h,kk) channel, sequential over T.
// Also accumulates GroupNorm sum / sumsq per (b,h) and writes stats.
// ---------------------------------------------------------------------------
__global__ __launch_bounds__(64)
void wkv_scan(const float* __restrict__ time_decay,
              const float* __restrict__ time_first)
{
    const int bh = blockIdx.x;          // 0..63
    const int b  = bh >> 4;
    const int h  = bh & 15;
    const int kk = threadIdx.x;         // 0..63

    const float w  = expf(-expf(time_decay[h * Kh + kk]));
    const float eu = expf(time_first[h * Kh + kk]);

    const size_t base = (size_t)b * Tt * Dd + h * Kh + kk;

    float num = 0.f, den = 0.f;
    float s1 = 0.f, s2 = 0.f;

    #pragma unroll 1
    for (int t0 = 0; t0 < Tt; t0 += 8) {
        float kt[8], vt[8], rt[8];
        #pragma unroll
        for (int j = 0; j < 8; ++j) {
            size_t idx = base + (size_t)(t0 + j) * Dd;
            kt[j] = g_k[idx];
            vt[j] = g_v[idx];
            rt[j] = g_r[idx];
        }
        #pragma unroll
        for (int j = 0; j < 8; ++j) {
            float ek  = __expf(kt[j]);
            float ekv = ek * vt[j];
            float eek = eu * ek;
            float wkv = __fdividef(num + eu * ekv, den + eek + 1e-9f);
            float o   = rt[j] * wkv;
            g_o[base + (size_t)(t0 + j) * Dd] = o;
            s1 += o;
            s2 += o * o;
            num = num * w + ekv;
            den = den * w + ek;
        }
    }

    // GroupNorm stats over (T,K) for this (b,h)
    __shared__ float sh1[64], sh2[64];
    sh1[kk] = s1;
    sh2[kk] = s2;
    __syncthreads();
    #pragma unroll
    for (int off = 32; off > 0; off >>= 1) {
        if (kk < off) {
            sh1[kk] += sh1[kk + off];
            sh2[kk] += sh2[kk + off];
        }
        __syncthreads();
    }
    if (kk == 0) {
        const float invN = 1.f / (float)(Tt * Kh);
        float mean = sh1[0] * invN;
        float var  = sh2[0] * invN - mean * mean;
        g_stats[bh] = make_float2(mean, rsqrtf(var + 1e-5f));
    }
}

// ---------------------------------------------------------------------------
// GEMM 2: fused GroupNorm-normalize + output projection.
//   A[m][d] = (g_o[m][d] - mu[b,h]) * rstd[b,h] * gw[d] + gb[d]
//   out[m][e] = sum_d A[m][d] * W_o[e][d]
// ---------------------------------------------------------------------------
__global__ __launch_bounds__(256)
void out_gemm(const float* __restrict__ Wo,
              const float* __restrict__ gw,
              const float* __restrict__ gb,
              float* __restrict__ out)
{
    __shared__ float As[BKT][BM + 4];
    __shared__ float Bs[BKT][BN + 4];

    const int tid = threadIdx.x;
    const int m0 = blockIdx.x * BM;
    const int n0 = blockIdx.y * BN;
    const int tx = tid & 15;
    const int ty = tid >> 4;

    float acc[8][8];
    #pragma unroll
    for (int i = 0; i < 8; ++i)
        #pragma unroll
        for (int j = 0; j < 8; ++j) acc[i][j] = 0.f;

    for (int k0 = 0; k0 < Dd; k0 += BKT) {
        #pragma unroll
        for (int it = 0; it < 2; ++it) {
            int s  = tid + it * 256;
            int m  = s >> 2;
            int d4 = (s & 3) << 2;
            int gm = m0 + m;
            int gd = k0 + d4;
            int b  = gm >> 12;              // T = 4096
            int h  = gd >> 6;               // K = 64 (same h across a float4)
            float2 st = g_stats[(b << 4) + h];
            float4 ov  = *(const float4*)(g_o + (size_t)gm * Dd + gd);
            float4 gwv = *(const float4*)(gw + gd);
            float4 gbv = *(const float4*)(gb + gd);
            As[d4 + 0][m] = (ov.x - st.x) * st.y * gwv.x + gbv.x;
            As[d4 + 1][m] = (ov.y - st.x) * st.y * gwv.y + gbv.y;
            As[d4 + 2][m] = (ov.z - st.x) * st.y * gwv.z + gbv.z;
            As[d4 + 3][m] = (ov.w - st.x) * st.y * gwv.w + gbv.w;
        }
        #pragma unroll
        for (int it = 0; it < 2; ++it) {
            int s  = tid + it * 256;
            int e  = s >> 2;
            int d4 = (s & 3) << 2;
            int ge = n0 + e;
            int gd = k0 + d4;
            float4 wv = *(const float4*)(Wo + (size_t)ge * Dd + gd);
            Bs[d4 + 0][e] = wv.x;
            Bs[d4 + 1][e] = wv.y;
            Bs[d4 + 2][e] = wv.z;
            Bs[d4 + 3][e] = wv.w;
        }
        __syncthreads();

        #pragma unroll
        for (int kk = 0; kk < BKT; ++kk) {
            float a[8], bb[8];
            #pragma unroll
            for (int i = 0; i < 8; ++i) a[i] = As[kk][ty * 8 + i];
            #pragma unroll
            for (int j = 0; j < 8; ++j) bb[j] = Bs[kk][tx * 8 + j];
            #pragma unroll
            for (int i = 0; i < 8; ++i)
                #pragma unroll
                for (int j = 0; j < 8; ++j)
                    acc[i][j] = fmaf(a[i], bb[j], acc[i][j]);
        }
        __syncthreads();
    }

    #pragma unroll
    for (int i = 0; i < 8; ++i) {
        int gm = m0 + ty * 8 + i;
        int ge = n0 + tx * 8;
        *(float4*)(out + (size_t)gm * Dd + ge) =
            make_float4(acc[i][0], acc[i][1], acc[i][2], acc[i][3]);
        *(float4*)(out + (size_t)gm * Dd + ge + 4) =
            make_float4(acc[i][4], acc[i][5], acc[i][6], acc[i][7]);
    }
}

// ---------------------------------------------------------------------------
// kernel_launch
// Input order (metadata): x, time_mix_r, time_mix_k, time_mix_v, time_decay,
//                         time_first, W_r, W_k, W_v, W_o, gn_weight, gn_bias
// ---------------------------------------------------------------------------
extern "C" void kernel_launch(void* const* d_in, const int* in_sizes, int n_in,
                              void* d_out, int out_size)
{
    const float* x   = (const float*)d_in[0];
    const float* tmr = (const float*)d_in[1];
    const float* tmk = (const float*)d_in[2];
    const float* tmv = (const float*)d_in[3];
    const float* td  = (const float*)d_in[4];
    const float* tf  = (const float*)d_in[5];
    const float* Wr  = (const float*)d_in[6];
    const float* Wk  = (const float*)d_in[7];
    const float* Wv  = (const float*)d_in[8];
    const float* Wo  = (const float*)d_in[9];
    const float* gw  = (const float*)d_in[10];
    const float* gb  = (const float*)d_in[11];
    float* out = (float*)d_out;

    dim3 grid(Mtot / BM, Dd / BN);   // (128, 8)
    dim3 block(256);

    mix_proj_gemm<<<grid, block>>>(x, tmr, Wr, 0);  // r (sigmoid)
    mix_proj_gemm<<<grid, block>>>(x, tmk, Wk, 1);  // k
    mix_proj_gemm<<<grid, block>>>(x, tmv, Wv, 2);  // v

    wkv_scan<<<Bq * Hh, Kh>>>(td, tf);

    out_gemm<<<grid, block>>>(Wo, gw, gb, out);
}